// round 7
// baseline (speedup 1.0000x reference)
#include <cuda_runtime.h>
#include <cuda_bf16.h>

// Problem shapes (fixed by the dataset):
//   emb_nodes : [B=4, N=768, d=16]  float32  (d_in[0], 49152 elems)
//   edges     : [B=4, 2, E=12288]   int32    (d_in[1], 98304 elems; JAX x64-off downcasts int64->int32)
//   W         : [2d=32]             float32  (d_in[2])
//   b         : [1]                 float32  (d_in[3])
// Output tuple flattened into d_out (float32), in reference-return order:
//   edge_embeddings [B, N*N, 2d] : 75,497,472 elems @ offset 0
//   logits          [B, N*N]     :  2,359,296 elems @ offset 75,497,472
//   truth           [B, N*N]     :  2,359,296 elems @ offset 77,856,768

namespace {
constexpr int B_  = 4;
constexpr int N_  = 768;
constexpr int D_  = 16;
constexpr int E_  = 12288;
constexpr long long NN_ = (long long)N_ * N_;          // 589824
constexpr long long PAIRS_ = (long long)B_ * NN_;      // 2359296
constexpr long long EE_ELEMS_ = PAIRS_ * 2 * D_;       // 75497472
}

// Main kernel: 8 threads per pair. Thread t -> pair = t>>3, chunk = t&7.
// chunk 0..3 write float4 c of emb_i, chunk 4..7 write float4 (c-4) of emb_j.
// chunk 0 also computes the logit + equality check; chunk 1 zeroes truth.
__global__ __launch_bounds__(256)
void edge_pairs_kernel(const float* __restrict__ emb,
                       const float* __restrict__ W,
                       const float* __restrict__ bias,
                       float* __restrict__ ee,
                       float* __restrict__ logits,
                       float* __restrict__ truth)
{
    long long t = (long long)blockIdx.x * blockDim.x + threadIdx.x;
    if (t >= PAIRS_ * 8) return;

    long long pair = t >> 3;
    int chunk = (int)(t & 7);

    int b   = (int)(pair / NN_);
    int rem = (int)(pair - (long long)b * NN_);
    int i   = rem / N_;
    int j   = rem - i * N_;

    const float4* rowi = (const float4*)(emb + ((long long)b * N_ + i) * D_);
    const float4* rowj = (const float4*)(emb + ((long long)b * N_ + j) * D_);
    float4* out = (float4*)(ee + pair * (2 * D_));

    // Coalesced 128B line per pair: 8 consecutive threads, 8 consecutive float4s.
    float4 v = (chunk < 4) ? __ldg(rowi + chunk) : __ldg(rowj + (chunk - 4));
    out[chunk] = v;

    if (chunk == 0) {
        float acc = __ldg(bias);
        bool eq = true;
        #pragma unroll
        for (int c = 0; c < 4; ++c) {
            float4 a  = __ldg(rowi + c);
            float4 bb = __ldg(rowj + c);
            float4 w1 = __ldg(((const float4*)W) + c);
            float4 w2 = __ldg(((const float4*)W) + c + 4);
            acc = fmaf(a.x,  w1.x, acc);
            acc = fmaf(a.y,  w1.y, acc);
            acc = fmaf(a.z,  w1.z, acc);
            acc = fmaf(a.w,  w1.w, acc);
            acc = fmaf(bb.x, w2.x, acc);
            acc = fmaf(bb.y, w2.y, acc);
            acc = fmaf(bb.z, w2.z, acc);
            acc = fmaf(bb.w, w2.w, acc);
            eq = eq && (a.x == bb.x) && (a.y == bb.y)
                    && (a.z == bb.z) && (a.w == bb.w);
        }
        logits[pair] = eq ? -10.0f : acc;
    } else if (chunk == 1) {
        truth[pair] = 0.0f;
    }
}

// Scatter ground-truth 1.0 at edges[b,0,e]*N + edges[b,1,e]  (edges are int32).
__global__ __launch_bounds__(256)
void truth_scatter_kernel(const int* __restrict__ edges,
                          float* __restrict__ truth)
{
    int t = blockIdx.x * blockDim.x + threadIdx.x;
    if (t >= B_ * E_) return;
    int b = t / E_;
    int e = t - b * E_;
    int src = edges[b * 2 * E_ + e];
    int dst = edges[b * 2 * E_ + E_ + e];
    truth[(long long)b * NN_ + (long long)src * N_ + dst] = 1.0f;
}

extern "C" void kernel_launch(void* const* d_in, const int* in_sizes, int n_in,
                              void* d_out, int out_size)
{
    const float* emb   = (const float*)d_in[0];
    const int*   edges = (const int*)d_in[1];
    const float* W     = (const float*)d_in[2];
    const float* bias  = (const float*)d_in[3];

    float* out    = (float*)d_out;
    float* ee     = out;
    float* logits = out + EE_ELEMS_;
    float* truth  = out + EE_ELEMS_ + PAIRS_;

    {
        long long total = PAIRS_ * 8;
        int threads = 256;
        int blocks = (int)((total + threads - 1) / threads);
        edge_pairs_kernel<<<blocks, threads>>>(emb, W, bias, ee, logits, truth);
    }
    {
        int total = B_ * E_;
        int threads = 256;
        int blocks = (total + threads - 1) / threads;
        truth_scatter_kernel<<<blocks, threads>>>(edges, truth);
    }
}

// round 8
// speedup vs baseline: 2.0057x; 2.0057x over previous
#include <cuda_runtime.h>
#include <cuda_bf16.h>

// Shapes (fixed):
//   emb_nodes : [B=4, N=768, d=16] f32   (d_in[0])
//   edges     : [B=4, 2, E=12288]  i32   (d_in[1])
//   W         : [32] f32                 (d_in[2])
//   b         : [1]  f32                 (d_in[3])
// d_out (f32): ee [4,589824,32] @0 | logits [4,589824] @75497472 | truth @77856768

namespace {
constexpr unsigned B_  = 4;
constexpr unsigned N_  = 768;
constexpr unsigned D_  = 16;
constexpr unsigned E_  = 12288;
constexpr unsigned NN_    = N_ * N_;          // 589824
constexpr unsigned PAIRS_ = B_ * NN_;         // 2359296
constexpr unsigned long long EE_ELEMS_ = (unsigned long long)PAIRS_ * 2 * D_; // 75497472
}

// ---------------------------------------------------------------------------
// Kernel A: pure copy. 8 threads per pair, one float4 each, zero divergence.
// chunk 0..3 -> float4 c of row i ; chunk 4..7 -> float4 (c-4) of row j.
// 8 consecutive threads emit one contiguous 128B line of ee.
// ---------------------------------------------------------------------------
__global__ __launch_bounds__(256)
void ee_copy_kernel(const float4* __restrict__ emb4, float4* __restrict__ ee4)
{
    unsigned t = blockIdx.x * blockDim.x + threadIdx.x;   // < PAIRS_*8 = 18874368
    unsigned pair  = t >> 3;
    unsigned chunk = t & 7;

    unsigned b   = pair / NN_;
    unsigned rem = pair - b * NN_;
    unsigned i   = rem / N_;
    unsigned j   = rem - i * N_;

    unsigned node = (chunk < 4) ? i : j;
    unsigned c    = chunk & 3;
    float4 v = __ldg(emb4 + (b * N_ + node) * 4u + c);
    // streaming store: output is write-once, keep it from thrashing L2
    __stcs(ee4 + (unsigned long long)pair * 8u + chunk, v);
}

// ---------------------------------------------------------------------------
// Kernel B: logits + truth zeroing. One thread per 4 consecutive pairs
// (same row i, columns j..j+3). float4 store for both logits and truth.
// ---------------------------------------------------------------------------
__global__ __launch_bounds__(256)
void logits_kernel(const float4* __restrict__ emb4,
                   const float4* __restrict__ W4,
                   const float*  __restrict__ bias,
                   float4* __restrict__ logits4,
                   float4* __restrict__ truth4)
{
    unsigned t = blockIdx.x * blockDim.x + threadIdx.x;   // < PAIRS_/4 = 589824
    if (t >= PAIRS_ / 4) return;

    unsigned base = t * 4;                 // first pair index
    unsigned b    = base / NN_;
    unsigned rem  = base - b * NN_;
    unsigned i    = rem / N_;
    unsigned j0   = rem - i * N_;          // multiple of 4, j0..j0+3 in-row

    float4 a[4], w1[4], w2[4];
    #pragma unroll
    for (int c = 0; c < 4; ++c) {
        a[c]  = __ldg(emb4 + (b * N_ + i) * 4u + c);
        w1[c] = __ldg(W4 + c);
        w2[c] = __ldg(W4 + c + 4);
    }
    float bia = __ldg(bias);
    float ai_dot = bia;
    #pragma unroll
    for (int c = 0; c < 4; ++c) {
        ai_dot = fmaf(a[c].x, w1[c].x, ai_dot);
        ai_dot = fmaf(a[c].y, w1[c].y, ai_dot);
        ai_dot = fmaf(a[c].z, w1[c].z, ai_dot);
        ai_dot = fmaf(a[c].w, w1[c].w, ai_dot);
    }

    float lg[4];
    #pragma unroll
    for (int q = 0; q < 4; ++q) {
        unsigned j = j0 + q;
        float acc = ai_dot;
        bool eq = true;
        #pragma unroll
        for (int c = 0; c < 4; ++c) {
            float4 bb = __ldg(emb4 + (b * N_ + j) * 4u + c);
            acc = fmaf(bb.x, w2[c].x, acc);
            acc = fmaf(bb.y, w2[c].y, acc);
            acc = fmaf(bb.z, w2[c].z, acc);
            acc = fmaf(bb.w, w2[c].w, acc);
            eq = eq && (a[c].x == bb.x) && (a[c].y == bb.y)
                    && (a[c].z == bb.z) && (a[c].w == bb.w);
        }
        lg[q] = eq ? -10.0f : acc;
    }

    logits4[t] = make_float4(lg[0], lg[1], lg[2], lg[3]);
    truth4[t]  = make_float4(0.f, 0.f, 0.f, 0.f);
}

// ---------------------------------------------------------------------------
// Kernel C: scatter 1.0 at edges[b,0,e]*N + edges[b,1,e]  (int32 indices).
// ---------------------------------------------------------------------------
__global__ __launch_bounds__(256)
void truth_scatter_kernel(const int* __restrict__ edges,
                          float* __restrict__ truth)
{
    unsigned t = blockIdx.x * blockDim.x + threadIdx.x;
    if (t >= B_ * E_) return;
    unsigned b = t / E_;
    unsigned e = t - b * E_;
    int src = edges[b * 2 * E_ + e];
    int dst = edges[b * 2 * E_ + E_ + e];
    truth[(unsigned long long)b * NN_ + (unsigned)src * N_ + (unsigned)dst] = 1.0f;
}

extern "C" void kernel_launch(void* const* d_in, const int* in_sizes, int n_in,
                              void* d_out, int out_size)
{
    const float* emb   = (const float*)d_in[0];
    const int*   edges = (const int*)d_in[1];
    const float* W     = (const float*)d_in[2];
    const float* bias  = (const float*)d_in[3];

    float* out    = (float*)d_out;
    float* ee     = out;
    float* logits = out + EE_ELEMS_;
    float* truth  = out + EE_ELEMS_ + PAIRS_;

    {   // Kernel A: 18,874,368 threads
        unsigned total = PAIRS_ * 8;
        ee_copy_kernel<<<total / 256, 256>>>((const float4*)emb, (float4*)ee);
    }
    {   // Kernel B: 589,824 threads
        unsigned total = PAIRS_ / 4;
        logits_kernel<<<(total + 255) / 256, 256>>>((const float4*)emb,
                                                    (const float4*)W, bias,
                                                    (float4*)logits,
                                                    (float4*)truth);
    }
    {   // Kernel C
        unsigned total = B_ * E_;
        truth_scatter_kernel<<<(total + 255) / 256, 256>>>(edges, truth);
    }
}

// round 10
// speedup vs baseline: 3.0229x; 1.5072x over previous
#include <cuda_runtime.h>
#include <cuda_bf16.h>

// Shapes (fixed):
//   emb_nodes : [B=4, N=768, d=16] f32   (d_in[0])
//   edges     : [B=4, 2, E=12288]  i32   (d_in[1])
//   W         : [32] f32                 (d_in[2])
//   b         : [1]  f32                 (d_in[3])
// d_out (f32): ee [4,589824,32] @0 | logits [4,589824] @75497472 | truth @77856768

namespace {
constexpr unsigned B_  = 4;
constexpr unsigned N_  = 768;
constexpr unsigned E_  = 12288;
constexpr unsigned NN_    = N_ * N_;          // 589824
constexpr unsigned PAIRS_ = B_ * NN_;         // 2359296
constexpr unsigned NODES_ = B_ * N_;          // 3072
constexpr unsigned long long EE_ELEMS_ = (unsigned long long)PAIRS_ * 32; // 75497472
}

// Per-node precomputed scratch (device globals: no allocation allowed).
__device__ float    g_dot1[NODES_];   // e_v . W[0:16] + bias
__device__ float    g_dot2[NODES_];   // e_v . W[16:32]
__device__ unsigned g_hash[NODES_];   // row-bit hash (0-canonicalized)

// ---------------------------------------------------------------------------
// Kernel A: edge_embeddings copy. One block per (b, i) row.
// Output segment for (b,i) is 768 pairs * 128B = 96KB contiguous.
// Row i is held in registers; only j-chunks load (L1/L2-resident emb).
// ---------------------------------------------------------------------------
__global__ __launch_bounds__(256)
void ee_copy_kernel(const float4* __restrict__ emb4, float4* __restrict__ ee4)
{
    unsigned blk = blockIdx.x;            // 0 .. 3071  = b*768 + i
    unsigned tid = threadIdx.x;

    // row i in registers
    float4 ri0 = __ldg(emb4 + blk * 4u + 0);
    float4 ri1 = __ldg(emb4 + blk * 4u + 1);
    float4 ri2 = __ldg(emb4 + blk * 4u + 2);
    float4 ri3 = __ldg(emb4 + blk * 4u + 3);

    unsigned b = blk / N_;                // batch
    const float4* embB = emb4 + b * N_ * 4u;          // rows of this batch
    float4* dst = ee4 + (unsigned long long)blk * (N_ * 8u); // 6144 float4

    // 6144 float4s / 256 threads = 24 per thread
    #pragma unroll 8
    for (unsigned it = 0; it < 24; ++it) {
        unsigned f     = it * 256u + tid;   // 0 .. 6143
        unsigned j     = f >> 3;            // pair column
        unsigned chunk = f & 7u;
        float4 v;
        if (chunk < 4) {
            v = (chunk == 0) ? ri0 : (chunk == 1) ? ri1 : (chunk == 2) ? ri2 : ri3;
        } else {
            v = __ldg(embB + j * 4u + (chunk - 4u));
        }
        __stcs(dst + f, v);
    }
}

// ---------------------------------------------------------------------------
// Kernel B0: per-node dot products + row hash. 3072 threads.
// ---------------------------------------------------------------------------
__global__ __launch_bounds__(256)
void node_pre_kernel(const float4* __restrict__ emb4,
                     const float4* __restrict__ W4,
                     const float*  __restrict__ bias)
{
    unsigned v = blockIdx.x * blockDim.x + threadIdx.x;
    if (v >= NODES_) return;

    float d1 = __ldg(bias);
    float d2 = 0.f;
    unsigned h = 0u;
    #pragma unroll
    for (int c = 0; c < 4; ++c) {
        float4 a  = __ldg(emb4 + v * 4u + c);
        float4 w1 = __ldg(W4 + c);
        float4 w2 = __ldg(W4 + c + 4);
        d1 = fmaf(a.x, w1.x, d1); d1 = fmaf(a.y, w1.y, d1);
        d1 = fmaf(a.z, w1.z, d1); d1 = fmaf(a.w, w1.w, d1);
        d2 = fmaf(a.x, w2.x, d2); d2 = fmaf(a.y, w2.y, d2);
        d2 = fmaf(a.z, w2.z, d2); d2 = fmaf(a.w, w2.w, d2);
        // position-dependent hash of bit patterns; canonicalize +-0
        const float  vals[4] = {a.x, a.y, a.z, a.w};
        #pragma unroll
        for (int k = 0; k < 4; ++k) {
            unsigned u = __float_as_uint(vals[k]);
            if (vals[k] == 0.f) u = 0u;
            int rot = (c * 4 + k) & 31;
            h ^= __funnelshift_l(u, u, rot);
        }
    }
    g_dot1[v] = d1;
    g_dot2[v] = d2;
    g_hash[v] = h;
}

// exact row comparison under float== (rare path: hash matched)
__device__ __forceinline__ bool rows_equal(const float4* __restrict__ emb4,
                                           unsigned va, unsigned vb)
{
    bool eq = true;
    #pragma unroll
    for (int c = 0; c < 4; ++c) {
        float4 a = __ldg(emb4 + va * 4u + c);
        float4 b = __ldg(emb4 + vb * 4u + c);
        eq = eq && (a.x == b.x) && (a.y == b.y) && (a.z == b.z) && (a.w == b.w);
    }
    return eq;
}

// ---------------------------------------------------------------------------
// Kernel B1: logits + truth zeroing. One thread per 4 consecutive pairs.
// ---------------------------------------------------------------------------
__global__ __launch_bounds__(256)
void logits_kernel(const float4* __restrict__ emb4,
                   float4* __restrict__ logits4,
                   float4* __restrict__ truth4)
{
    unsigned t = blockIdx.x * blockDim.x + threadIdx.x;   // < PAIRS_/4 = 589824
    if (t >= PAIRS_ / 4) return;

    constexpr unsigned Q = NN_ / 4;     // 147456 quads per batch
    unsigned b    = t / Q;
    unsigned rem  = t - b * Q;
    unsigned i    = rem / (N_ / 4);     // rem / 192
    unsigned j0   = (rem - i * (N_ / 4)) * 4u;

    unsigned ni = b * N_ + i;
    float    d1 = g_dot1[ni];
    unsigned hi = g_hash[ni];

    unsigned nj = b * N_ + j0;
    float4 d2 = *(const float4*)&g_dot2[nj];
    uint4  hj = *(const uint4*)&g_hash[nj];

    float lg[4] = { d1 + d2.x, d1 + d2.y, d1 + d2.z, d1 + d2.w };
    const unsigned hjs[4] = { hj.x, hj.y, hj.z, hj.w };
    #pragma unroll
    for (int q = 0; q < 4; ++q) {
        if (hi == hjs[q]) {                       // rare: verify exactly
            if (rows_equal(emb4, ni, nj + q)) lg[q] = -10.0f;
        }
    }

    logits4[t] = make_float4(lg[0], lg[1], lg[2], lg[3]);
    truth4[t]  = make_float4(0.f, 0.f, 0.f, 0.f);
}

// ---------------------------------------------------------------------------
// Kernel C: scatter 1.0 at edges[b,0,e]*N + edges[b,1,e]  (int32 indices).
// ---------------------------------------------------------------------------
__global__ __launch_bounds__(256)
void truth_scatter_kernel(const int* __restrict__ edges,
                          float* __restrict__ truth)
{
    unsigned t = blockIdx.x * blockDim.x + threadIdx.x;
    if (t >= B_ * E_) return;
    unsigned b = t / E_;
    unsigned e = t - b * E_;
    int src = edges[b * 2 * E_ + e];
    int dst = edges[b * 2 * E_ + E_ + e];
    truth[(unsigned long long)b * NN_ + (unsigned)src * N_ + (unsigned)dst] = 1.0f;
}

extern "C" void kernel_launch(void* const* d_in, const int* in_sizes, int n_in,
                              void* d_out, int out_size)
{
    const float* emb   = (const float*)d_in[0];
    const int*   edges = (const int*)d_in[1];
    const float* W     = (const float*)d_in[2];
    const float* bias  = (const float*)d_in[3];

    float* out    = (float*)d_out;
    float* ee     = out;
    float* logits = out + EE_ELEMS_;
    float* truth  = out + EE_ELEMS_ + PAIRS_;

    // B0: per-node precompute (3072 threads) — independent of A, launch first
    node_pre_kernel<<<(NODES_ + 255) / 256, 256>>>((const float4*)emb,
                                                   (const float4*)W, bias);
    // A: big copy, one block per (b,i) row
    ee_copy_kernel<<<NODES_, 256>>>((const float4*)emb, (float4*)ee);
    // B1: logits + truth zero
    logits_kernel<<<(PAIRS_ / 4 + 255) / 256, 256>>>((const float4*)emb,
                                                     (float4*)logits,
                                                     (float4*)truth);
    // C: ground-truth scatter (after zeroing, same stream)
    truth_scatter_kernel<<<(B_ * E_ + 255) / 256, 256>>>(edges, truth);
}

// round 11
// speedup vs baseline: 3.1382x; 1.0381x over previous
#include <cuda_runtime.h>
#include <cuda_bf16.h>

// Shapes (fixed):
//   emb_nodes : [B=4, N=768, d=16] f32   (d_in[0])
//   edges     : [B=4, 2, E=12288]  i32   (d_in[1])
//   W         : [32] f32                 (d_in[2])
//   b         : [1]  f32                 (d_in[3])
// d_out (f32): ee [4,589824,32] @0 | logits [4,589824] @75497472 | truth @77856768

namespace {
constexpr unsigned B_  = 4;
constexpr unsigned N_  = 768;
constexpr unsigned E_  = 12288;
constexpr unsigned NN_    = N_ * N_;          // 589824
constexpr unsigned PAIRS_ = B_ * NN_;         // 2359296
constexpr unsigned NODES_ = B_ * N_;          // 3072
constexpr unsigned BM_WORDS_ = PAIRS_ / 32;   // 73728 (288 KB bitmap)
constexpr unsigned long long EE_ELEMS_ = (unsigned long long)PAIRS_ * 32; // 75497472
}

// Device-global scratch (no allocation allowed).
__device__ float    g_dot1[NODES_];     // e_v . W[0:16] + bias
__device__ float    g_dot2[NODES_];     // e_v . W[16:32]
__device__ unsigned g_hash[NODES_];     // row-bit hash (0-canonicalized)
__device__ unsigned g_bitmap[BM_WORDS_];// ground-truth edge bitmap

// ---------------------------------------------------------------------------
// Kernel 1 (prep): zero bitmap + per-node dots/hash. 73728 threads.
// ---------------------------------------------------------------------------
__global__ __launch_bounds__(256)
void prep_kernel(const float4* __restrict__ emb4,
                 const float4* __restrict__ W4,
                 const float*  __restrict__ bias)
{
    unsigned t = blockIdx.x * blockDim.x + threadIdx.x;
    if (t < BM_WORDS_) g_bitmap[t] = 0u;

    if (t < NODES_) {
        float d1 = __ldg(bias);
        float d2 = 0.f;
        unsigned h = 0u;
        #pragma unroll
        for (int c = 0; c < 4; ++c) {
            float4 a  = __ldg(emb4 + t * 4u + c);
            float4 w1 = __ldg(W4 + c);
            float4 w2 = __ldg(W4 + c + 4);
            d1 = fmaf(a.x, w1.x, d1); d1 = fmaf(a.y, w1.y, d1);
            d1 = fmaf(a.z, w1.z, d1); d1 = fmaf(a.w, w1.w, d1);
            d2 = fmaf(a.x, w2.x, d2); d2 = fmaf(a.y, w2.y, d2);
            d2 = fmaf(a.z, w2.z, d2); d2 = fmaf(a.w, w2.w, d2);
            const float vals[4] = {a.x, a.y, a.z, a.w};
            #pragma unroll
            for (int k = 0; k < 4; ++k) {
                unsigned u = __float_as_uint(vals[k]);
                if (vals[k] == 0.f) u = 0u;          // canonicalize +-0
                int rot = (c * 4 + k) & 31;
                h ^= __funnelshift_l(u, u, rot);
            }
        }
        g_dot1[t] = d1;
        g_dot2[t] = d2;
        g_hash[t] = h;
    }
}

// ---------------------------------------------------------------------------
// Kernel 2: scatter edges into the bitmap (L2-resident, atomicOr).
// ---------------------------------------------------------------------------
__global__ __launch_bounds__(256)
void edge_bitmap_kernel(const int* __restrict__ edges)
{
    unsigned t = blockIdx.x * blockDim.x + threadIdx.x;
    if (t >= B_ * E_) return;
    unsigned b = t / E_;
    unsigned e = t - b * E_;
    unsigned src = (unsigned)edges[b * 2 * E_ + e];
    unsigned dst = (unsigned)edges[b * 2 * E_ + E_ + e];
    unsigned pair = b * NN_ + src * N_ + dst;
    atomicOr(&g_bitmap[pair >> 5], 1u << (pair & 31));
}

// exact row comparison under float== (rare path: hash matched)
__device__ __forceinline__ bool rows_equal(const float4* __restrict__ emb4,
                                           unsigned va, unsigned vb)
{
    bool eq = true;
    #pragma unroll
    for (int c = 0; c < 4; ++c) {
        float4 a = __ldg(emb4 + va * 4u + c);
        float4 b = __ldg(emb4 + vb * 4u + c);
        eq = eq && (a.x == b.x) && (a.y == b.y) && (a.z == b.z) && (a.w == b.w);
    }
    return eq;
}

// ---------------------------------------------------------------------------
// Kernel 3 (mega): one block per (b,i) row. Writes the 96KB ee segment,
// then threads 0..191 emit the row's 768 logits + 768 truth values.
// ---------------------------------------------------------------------------
__global__ __launch_bounds__(256)
void mega_kernel(const float4* __restrict__ emb4,
                 float4* __restrict__ ee4,
                 float4* __restrict__ logits4,
                 float4* __restrict__ truth4)
{
    unsigned blk = blockIdx.x;            // b*768 + i
    unsigned tid = threadIdx.x;

    // row i in registers
    float4 ri0 = __ldg(emb4 + blk * 4u + 0);
    float4 ri1 = __ldg(emb4 + blk * 4u + 1);
    float4 ri2 = __ldg(emb4 + blk * 4u + 2);
    float4 ri3 = __ldg(emb4 + blk * 4u + 3);

    unsigned b = blk / N_;
    const float4* embB = emb4 + b * N_ * 4u;
    float4* dst = ee4 + (unsigned long long)blk * (N_ * 8u);   // 6144 float4

    // ---- edge_embeddings: 6144 float4 / 256 threads = 24 each ----
    #pragma unroll 8
    for (unsigned it = 0; it < 24; ++it) {
        unsigned f     = it * 256u + tid;
        unsigned j     = f >> 3;
        unsigned chunk = f & 7u;
        float4 v;
        if (chunk < 4) {
            v = (chunk == 0) ? ri0 : (chunk == 1) ? ri1 : (chunk == 2) ? ri2 : ri3;
        } else {
            v = __ldg(embB + j * 4u + (chunk - 4u));
        }
        __stcs(dst + f, v);
    }

    // ---- logits + truth: 768 pairs -> threads 0..191, 4 pairs each ----
    if (tid < N_ / 4) {
        unsigned j0 = tid * 4u;
        unsigned ni = blk;
        float    d1 = g_dot1[ni];
        unsigned hi = g_hash[ni];

        unsigned nj = b * N_ + j0;
        float4 d2 = *(const float4*)&g_dot2[nj];
        uint4  hj = *(const uint4*)&g_hash[nj];

        float lg[4] = { d1 + d2.x, d1 + d2.y, d1 + d2.z, d1 + d2.w };
        const unsigned hjs[4] = { hj.x, hj.y, hj.z, hj.w };
        #pragma unroll
        for (int q = 0; q < 4; ++q) {
            if (hi == hjs[q]) {                    // rare: verify exactly
                if (rows_equal(emb4, ni, nj + q)) lg[q] = -10.0f;
            }
        }

        unsigned pair0 = blk * N_ + j0;            // first of the 4 pairs
        unsigned w     = g_bitmap[pair0 >> 5];
        unsigned bit0  = pair0 & 31u;
        float4 tr = make_float4((float)((w >> (bit0 + 0)) & 1u),
                                (float)((w >> (bit0 + 1)) & 1u),
                                (float)((w >> (bit0 + 2)) & 1u),
                                (float)((w >> (bit0 + 3)) & 1u));

        unsigned q4 = pair0 >> 2;                  // float4 index
        __stcs(logits4 + q4, make_float4(lg[0], lg[1], lg[2], lg[3]));
        __stcs(truth4 + q4, tr);
    }
}

extern "C" void kernel_launch(void* const* d_in, const int* in_sizes, int n_in,
                              void* d_out, int out_size)
{
    const float* emb   = (const float*)d_in[0];
    const int*   edges = (const int*)d_in[1];
    const float* W     = (const float*)d_in[2];
    const float* bias  = (const float*)d_in[3];

    float* out    = (float*)d_out;
    float* ee     = out;
    float* logits = out + EE_ELEMS_;
    float* truth  = out + EE_ELEMS_ + PAIRS_;

    // 1. prep: zero bitmap + node dots/hash (73728 threads)
    prep_kernel<<<BM_WORDS_ / 256, 256>>>((const float4*)emb,
                                          (const float4*)W, bias);
    // 2. edge scatter into bitmap (49152 threads)
    edge_bitmap_kernel<<<(B_ * E_) / 256, 256>>>(edges);
    // 3. mega: all 321MB of output in one kernel
    mega_kernel<<<NODES_, 256>>>((const float4*)emb, (float4*)ee,
                                 (float4*)logits, (float4*)truth);
}